// round 13
// baseline (speedup 1.0000x reference)
#include <cuda_runtime.h>
#include <cstdint>

#define BB 2
#define SS 4096
#define DD 128
#define HALF 64
#define TM 64            // rows per CTA (both kernels)
#define KU 192           // key union per tile
#define NT 256           // 8 warps

// Q/K/V scratch as tf32 bit patterns (Q pre-scaled by 1/sqrt(D))
__device__ uint32_t g_q[BB * SS * DD];
__device__ uint32_t g_k[BB * SS * DD];
__device__ uint32_t g_v[BB * SS * DD];

__device__ __forceinline__ uint32_t f2tf32(float f) {
    uint32_t u;
    asm("cvt.rna.tf32.f32 %0, %1;" : "=r"(u) : "f"(f));
    return u;
}
__device__ __forceinline__ uint32_t smem_u32(const void* p) {
    uint32_t a;
    asm("{ .reg .u64 t; cvta.to.shared.u64 t, %1; cvt.u32.u64 %0, t; }" : "=r"(a) : "l"(p));
    return a;
}
// 16B async copy, src_size<16 zero-fills
__device__ __forceinline__ void cpa(uint32_t dst, const void* src, int srcsz) {
    asm volatile("cp.async.cg.shared.global [%0], [%1], 16, %2;"
                 :: "r"(dst), "l"(src), "r"(srcsz) : "memory");
}
#define CP_COMMIT() asm volatile("cp.async.commit_group;" ::: "memory")
#define CP_WAIT(n)  asm volatile("cp.async.wait_group %0;" :: "n"(n) : "memory")

// D += A*B  (m16n8k8, tf32, row.col)
__device__ __forceinline__ void mma8(float* c, const uint32_t* a, uint32_t b0, uint32_t b1) {
    asm volatile(
        "mma.sync.aligned.m16n8k8.row.col.f32.tf32.tf32.f32 "
        "{%0,%1,%2,%3}, {%4,%5,%6,%7}, {%8,%9}, {%0,%1,%2,%3};"
        : "+f"(c[0]), "+f"(c[1]), "+f"(c[2]), "+f"(c[3])
        : "r"(a[0]), "r"(a[1]), "r"(a[2]), "r"(a[3]), "r"(b0), "r"(b1));
}

// smem pitches (words): A-pattern pitch%32==4 (132,196), B-pattern pitch%32==8 (136)
#define XP 132
#define WP 136
#define PP 196

// ---------------------------------------------------------------------------
// Kernel 1: QKV projection, W double-buffered, A-frags cached in regs,
// B-frags software-pipelined one k-step ahead. grid=128, 256 threads.
// ---------------------------------------------------------------------------
#define QXS_W (TM * XP)       // 8448
#define QWS_W (DD * WP)       // 17408
#define QKV_SMEM ((QXS_W + 2 * QWS_W) * 4)   // 173056

__global__ __launch_bounds__(NT, 1) void qkv_kernel(
    const float* __restrict__ x,
    const float* __restrict__ Wq, const float* __restrict__ bq,
    const float* __restrict__ Wk, const float* __restrict__ bk,
    const float* __restrict__ Wv, const float* __restrict__ bv)
{
    extern __shared__ uint32_t smem[];
    const float* Xs  = (const float*)smem;          // [64][XP] fp32
    const float* WsA = (const float*)(smem + QXS_W);// [128][WP] fp32
    const float* WsB = WsA + QWS_W;

    const uint32_t sb   = smem_u32(smem);
    const uint32_t xs_b = sb;
    const uint32_t wsA  = sb + QXS_W * 4;
    const uint32_t wsB  = wsA + QWS_W * 4;

    const int tid = threadIdx.x, w = tid >> 5, lane = tid & 31;
    const int gy = lane >> 2, gx = lane & 3;
    const int m0 = blockIdx.x * TM;
    const int r0 = 16 * (w & 3);
    const int c0 = 64 * (w >> 2);

    // group0: X + Wq ; group1: Wk
    for (int i = tid; i < TM * 32; i += NT) {
        int m = i >> 5, c = (i & 31) << 2;
        cpa(xs_b + (uint32_t)(m * XP + c) * 4, &x[(m0 + m) * DD + c], 16);
    }
    for (int i = tid; i < DD * 32; i += NT) {
        int d = i >> 5, c = (i & 31) << 2;
        cpa(wsA + (uint32_t)(d * WP + c) * 4, &Wq[d * DD + c], 16);
    }
    CP_COMMIT();
    for (int i = tid; i < DD * 32; i += NT) {
        int d = i >> 5, c = (i & 31) << 2;
        cpa(wsB + (uint32_t)(d * WP + c) * 4, &Wk[d * DD + c], 16);
    }
    CP_COMMIT();
    CP_WAIT(1);
    __syncthreads();

    // cache A fragments in registers (converted once, reused for Q/K/V)
    uint32_t a_all[16][4];
    #pragma unroll
    for (int ks = 0; ks < 16; ks++) {
        const int k0 = 8 * ks;
        a_all[ks][0] = f2tf32(Xs[(r0 + gy) * XP + k0 + gx]);
        a_all[ks][1] = f2tf32(Xs[(r0 + gy + 8) * XP + k0 + gx]);
        a_all[ks][2] = f2tf32(Xs[(r0 + gy) * XP + k0 + gx + 4]);
        a_all[ks][3] = f2tf32(Xs[(r0 + gy + 8) * XP + k0 + gx + 4]);
    }

    const float scale = 0.088388347648318447f;  // 1/sqrt(128)

    auto run_mma = [&](const float* Wf, float acc[8][4]) {
        #pragma unroll
        for (int t = 0; t < 8; t++)
            #pragma unroll
            for (int c = 0; c < 4; c++) acc[t][c] = 0.f;

        uint32_t bp[8][2];
        #pragma unroll
        for (int t = 0; t < 8; t++) {
            int n0 = c0 + 8 * t;
            bp[t][0] = f2tf32(Wf[(gx) * WP + n0 + gy]);
            bp[t][1] = f2tf32(Wf[(gx + 4) * WP + n0 + gy]);
        }
        #pragma unroll
        for (int ks = 0; ks < 16; ks++) {
            uint32_t bn[8][2];
            if (ks < 15) {
                const int k1 = 8 * (ks + 1);
                #pragma unroll
                for (int t = 0; t < 8; t++) {
                    int n0 = c0 + 8 * t;
                    bn[t][0] = f2tf32(Wf[(k1 + gx) * WP + n0 + gy]);
                    bn[t][1] = f2tf32(Wf[(k1 + gx + 4) * WP + n0 + gy]);
                }
            }
            #pragma unroll
            for (int t = 0; t < 8; t++) mma8(acc[t], a_all[ks], bp[t][0], bp[t][1]);
            if (ks < 15) {
                #pragma unroll
                for (int t = 0; t < 8; t++) { bp[t][0] = bn[t][0]; bp[t][1] = bn[t][1]; }
            }
        }
    };
    auto store_r = [&](uint32_t* dst, const float* bias, float scl, float acc[8][4]) {
        #pragma unroll
        for (int t = 0; t < 8; t++) {
            int col = c0 + 8 * t + 2 * gx;
            float bx = bias[col], by = bias[col + 1];
            uint2 v0 = make_uint2(f2tf32((acc[t][0] + bx) * scl), f2tf32((acc[t][1] + by) * scl));
            uint2 v1 = make_uint2(f2tf32((acc[t][2] + bx) * scl), f2tf32((acc[t][3] + by) * scl));
            *(uint2*)&dst[(size_t)(m0 + r0 + gy) * DD + col]     = v0;
            *(uint2*)&dst[(size_t)(m0 + r0 + gy + 8) * DD + col] = v1;
        }
    };

    float acc[8][4];
    run_mma(WsA, acc);               // Q  (Wk streaming behind)
    store_r(g_q, bq, scale, acc);

    CP_WAIT(0);                      // Wk landed
    __syncthreads();                 // all warps done reading WsA
    for (int i = tid; i < DD * 32; i += NT) {
        int d = i >> 5, c = (i & 31) << 2;
        cpa(wsA + (uint32_t)(d * WP + c) * 4, &Wv[d * DD + c], 16);
    }
    CP_COMMIT();

    run_mma(WsB, acc);               // K  (Wv streaming behind)
    store_r(g_k, bk, 1.f, acc);

    CP_WAIT(0);
    __syncthreads();

    run_mma(WsA, acc);               // V
    store_r(g_v, bv, 1.f, acc);
}

// ---------------------------------------------------------------------------
// Kernel 2: sliding-window attention, band-aware warps + pipelined fragments.
// grid=128, 256 threads.
// ---------------------------------------------------------------------------
#define AQS_W (TM * XP)       // 8448
#define AKV_W (KU * WP)       // 26112 (K at pitch XP, then V at pitch WP)
#define APS_W (TM * PP)       // 12544
#define ARS_W 128             // row-sum slots [half][64]
#define ATTN_SMEM ((AQS_W + AKV_W + APS_W + ARS_W) * 4)

__global__ __launch_bounds__(NT, 1) void attn_kernel(float* __restrict__ out)
{
    extern __shared__ uint32_t smem[];
    const uint32_t* Qs = smem;                         // [64][XP]
    const uint32_t* KV = smem + AQS_W;                 // K:[192][XP] / V:[192][WP]
    uint32_t*       Pu = smem + AQS_W + AKV_W;         // [64][PP] tf32 bits of exp(s)
    float*          rs = (float*)(smem + AQS_W + AKV_W + APS_W);  // [2][64]

    const uint32_t sb   = smem_u32(smem);
    const uint32_t qs_b = sb;
    const uint32_t kv_b = sb + AQS_W * 4;

    const int tid = threadIdx.x, w = tid >> 5, lane = tid & 31;
    const int gy = lane >> 2, gx = lane & 3;
    const int b  = blockIdx.x >> 6;
    const int q0 = (blockIdx.x & 63) * TM;
    const int kb = q0 - HALF;

    const uint32_t* qg = g_q + (size_t)b * SS * DD;
    const uint32_t* kg = g_k + (size_t)b * SS * DD;
    const uint32_t* vg = g_v + (size_t)b * SS * DD;

    // stage Q + K (zero-fill OOB rows)
    for (int i = tid; i < TM * 32; i += NT) {
        int m = i >> 5, c = (i & 31) << 2;
        cpa(qs_b + (uint32_t)(m * XP + c) * 4, &qg[(q0 + m) * DD + c], 16);
    }
    for (int i = tid; i < KU * 32; i += NT) {
        int j = i >> 5, c = (i & 31) << 2;
        int key = kb + j;
        int ok = (key >= 0 && key < SS);
        cpa(kv_b + (uint32_t)(j * XP + c) * 4, &kg[(size_t)(ok ? key : 0) * DD + c], ok ? 16 : 0);
    }
    CP_COMMIT();
    CP_WAIT(0);
    __syncthreads();

    const int r0   = 16 * (w & 3);          // row-group base
    const int half = w >> 2;                // band half (0/1)
    const int nb   = r0 + 72 * half;        // this warp's column base (9 tiles)

    // ---- S = Q @ K^T : warp = m16 x n72, A/B prefetched one k-step ----
    {
        float sacc[9][4];
        #pragma unroll
        for (int t = 0; t < 9; t++)
            #pragma unroll
            for (int c = 0; c < 4; c++) sacc[t][c] = 0.f;

        uint32_t ap[4], bp[9][2];
        ap[0] = Qs[(r0 + gy) * XP + gx];
        ap[1] = Qs[(r0 + gy + 8) * XP + gx];
        ap[2] = Qs[(r0 + gy) * XP + gx + 4];
        ap[3] = Qs[(r0 + gy + 8) * XP + gx + 4];
        #pragma unroll
        for (int t = 0; t < 9; t++) {
            int n0 = nb + 8 * t;
            bp[t][0] = KV[(n0 + gy) * XP + gx];
            bp[t][1] = KV[(n0 + gy) * XP + gx + 4];
        }

        #pragma unroll
        for (int ks = 0; ks < 16; ks++) {
            uint32_t an[4], bn[9][2];
            if (ks < 15) {
                const int k1 = 8 * (ks + 1);
                an[0] = Qs[(r0 + gy) * XP + k1 + gx];
                an[1] = Qs[(r0 + gy + 8) * XP + k1 + gx];
                an[2] = Qs[(r0 + gy) * XP + k1 + gx + 4];
                an[3] = Qs[(r0 + gy + 8) * XP + k1 + gx + 4];
                #pragma unroll
                for (int t = 0; t < 9; t++) {
                    int n0 = nb + 8 * t;
                    bn[t][0] = KV[(n0 + gy) * XP + k1 + gx];
                    bn[t][1] = KV[(n0 + gy) * XP + k1 + gx + 4];
                }
            }
            #pragma unroll
            for (int t = 0; t < 9; t++) mma8(sacc[t], ap, bp[t][0], bp[t][1]);
            if (ks < 15) {
                #pragma unroll
                for (int q = 0; q < 4; q++) ap[q] = an[q];
                #pragma unroll
                for (int t = 0; t < 9; t++) { bp[t][0] = bn[t][0]; bp[t][1] = bn[t][1]; }
            }
        }

        // mask + exp in registers; write tf32 bits of p; per-(half,row) sums
        float part[2] = {0.f, 0.f};
        #pragma unroll
        for (int t = 0; t < 9; t++) {
            #pragma unroll
            for (int h = 0; h < 2; h++) {
                int q  = r0 + gy + 8 * h;
                int j0 = nb + 8 * t + 2 * gx;
                float p0 = 0.f, p1 = 0.f;
                {
                    int j = j0, key = kb + j, dj = j - q;
                    if (dj >= 0 && dj <= 2 * HALF && key >= 0 && key < SS)
                        p0 = __expf(sacc[t][2 * h]);
                }
                {
                    int j = j0 + 1, key = kb + j, dj = j - q;
                    if (dj >= 0 && dj <= 2 * HALF && key >= 0 && key < SS)
                        p1 = __expf(sacc[t][2 * h + 1]);
                }
                part[h] += p0 + p1;
                *(uint2*)&Pu[q * PP + j0] = make_uint2(f2tf32(p0), f2tf32(p1));
            }
        }
        #pragma unroll
        for (int h = 0; h < 2; h++) {
            part[h] += __shfl_xor_sync(0xffffffffu, part[h], 1);
            part[h] += __shfl_xor_sync(0xffffffffu, part[h], 2);
        }
        if (gx == 0) {                       // unique writer per (half,row)
            rs[64 * half + r0 + gy]     = part[0];
            rs[64 * half + r0 + gy + 8] = part[1];
        }
    }
    __syncthreads();          // P + row sums complete; all KV reads done

    // ---- V copy (overwrites K buffer) ----
    for (int i = tid; i < KU * 32; i += NT) {
        int j = i >> 5, c = (i & 31) << 2;
        int key = kb + j;
        int ok = (key >= 0 && key < SS);
        cpa(kv_b + (uint32_t)(j * WP + c) * 4, &vg[(size_t)(ok ? key : 0) * DD + c], ok ? 16 : 0);
    }
    CP_COMMIT();
    CP_WAIT(0);
    __syncthreads();

    // ---- O = (P @ V) * inv[row] : warp = m16 x n64, 18 band k-steps ----
    {
        const int d0 = 64 * half;
        const int ksb = r0 >> 3;            // first k-tile intersecting the band
        float oacc[8][4];
        #pragma unroll
        for (int t = 0; t < 8; t++)
            #pragma unroll
            for (int c = 0; c < 4; c++) oacc[t][c] = 0.f;

        uint32_t ap[4], bp[8][2];
        {
            const int k0 = 8 * ksb;
            ap[0] = Pu[(r0 + gy) * PP + k0 + gx];
            ap[1] = Pu[(r0 + gy + 8) * PP + k0 + gx];
            ap[2] = Pu[(r0 + gy) * PP + k0 + gx + 4];
            ap[3] = Pu[(r0 + gy + 8) * PP + k0 + gx + 4];
            #pragma unroll
            for (int t = 0; t < 8; t++) {
                int n0 = d0 + 8 * t;
                bp[t][0] = KV[(k0 + gx) * WP + n0 + gy];
                bp[t][1] = KV[(k0 + gx + 4) * WP + n0 + gy];
            }
        }

        #pragma unroll
        for (int ks = 0; ks < 18; ks++) {
            uint32_t an[4], bn[8][2];
            if (ks < 17) {
                const int k1 = 8 * (ksb + ks + 1);
                an[0] = Pu[(r0 + gy) * PP + k1 + gx];
                an[1] = Pu[(r0 + gy + 8) * PP + k1 + gx];
                an[2] = Pu[(r0 + gy) * PP + k1 + gx + 4];
                an[3] = Pu[(r0 + gy + 8) * PP + k1 + gx + 4];
                #pragma unroll
                for (int t = 0; t < 8; t++) {
                    int n0 = d0 + 8 * t;
                    bn[t][0] = KV[(k1 + gx) * WP + n0 + gy];
                    bn[t][1] = KV[(k1 + gx + 4) * WP + n0 + gy];
                }
            }
            #pragma unroll
            for (int t = 0; t < 8; t++) mma8(oacc[t], ap, bp[t][0], bp[t][1]);
            if (ks < 17) {
                #pragma unroll
                for (int q = 0; q < 4; q++) ap[q] = an[q];
                #pragma unroll
                for (int t = 0; t < 8; t++) { bp[t][0] = bn[t][0]; bp[t][1] = bn[t][1]; }
            }
        }

        const float inv0 = 1.f / (rs[r0 + gy] + rs[64 + r0 + gy]);
        const float inv1 = 1.f / (rs[r0 + gy + 8] + rs[64 + r0 + gy + 8]);
        float* ob = out + (size_t)(b * SS + q0) * DD;
        #pragma unroll
        for (int t = 0; t < 8; t++) {
            int col = d0 + 8 * t + 2 * gx;
            *(float2*)&ob[(r0 + gy) * DD + col]     = make_float2(oacc[t][0] * inv0, oacc[t][1] * inv0);
            *(float2*)&ob[(r0 + gy + 8) * DD + col] = make_float2(oacc[t][2] * inv1, oacc[t][3] * inv1);
        }
    }
}

// ---------------------------------------------------------------------------
extern "C" void kernel_launch(void* const* d_in, const int* in_sizes, int n_in,
                              void* d_out, int out_size)
{
    const float* x  = (const float*)d_in[0];
    const float* Wq = (const float*)d_in[1];
    const float* bq = (const float*)d_in[2];
    const float* Wk = (const float*)d_in[3];
    const float* bk = (const float*)d_in[4];
    const float* Wv = (const float*)d_in[5];
    const float* bv = (const float*)d_in[6];
    float* out = (float*)d_out;

    cudaFuncSetAttribute(qkv_kernel,  cudaFuncAttributeMaxDynamicSharedMemorySize, QKV_SMEM);
    cudaFuncSetAttribute(attn_kernel, cudaFuncAttributeMaxDynamicSharedMemorySize, ATTN_SMEM);

    qkv_kernel<<<(BB * SS) / TM, NT, QKV_SMEM>>>(x, Wq, bq, Wk, bk, Wv, bv);
    attn_kernel<<<BB * (SS / TM), NT, ATTN_SMEM>>>(out);
}

// round 14
// speedup vs baseline: 1.2166x; 1.2166x over previous
#include <cuda_runtime.h>
#include <cuda_fp16.h>
#include <cstdint>

#define BB 2
#define SS 4096
#define DD 128
#define HALF 64
#define TM 64            // rows per CTA (both kernels)
#define KU 192           // key union per tile
#define NT 256           // 8 warps

// Q/K as fp16 [b][s][d] (Q pre-scaled by 1/sqrt(D)); V transposed [b][d][s]
__device__ __half g_q[BB * SS * DD];
__device__ __half g_k[BB * SS * DD];
__device__ __half g_vt[BB * DD * SS];

__device__ __forceinline__ uint32_t pkh(float a, float b) {
    __half2 h = __floats2half2_rn(a, b);
    return *(uint32_t*)&h;
}
__device__ __forceinline__ uint32_t smem_u32(const void* p) {
    uint32_t a;
    asm("{ .reg .u64 t; cvta.to.shared.u64 t, %1; cvt.u32.u64 %0, t; }" : "=r"(a) : "l"(p));
    return a;
}
__device__ __forceinline__ void cpa(uint32_t dst, const void* src, int srcsz) {
    asm volatile("cp.async.cg.shared.global [%0], [%1], 16, %2;"
                 :: "r"(dst), "l"(src), "r"(srcsz) : "memory");
}
#define CP_COMMIT() asm volatile("cp.async.commit_group;" ::: "memory")
#define CP_WAIT(n)  asm volatile("cp.async.wait_group %0;" :: "n"(n) : "memory")

// D += A*B  (m16n8k16, fp16 in, fp32 acc, row.col)
__device__ __forceinline__ void mma16(float* c, const uint32_t* a, uint32_t b0, uint32_t b1) {
    asm volatile(
        "mma.sync.aligned.m16n8k16.row.col.f32.f16.f16.f32 "
        "{%0,%1,%2,%3}, {%4,%5,%6,%7}, {%8,%9}, {%0,%1,%2,%3};"
        : "+f"(c[0]), "+f"(c[1]), "+f"(c[2]), "+f"(c[3])
        : "r"(a[0]), "r"(a[1]), "r"(a[2]), "r"(a[3]), "r"(b0), "r"(b1));
}

// word pitches, all ≡ 4 (mod 32) for conflict-free 8-row x 4-col fragment loads
#define XPF 132   // qkv X fp32 pitch (words)
#define WPF 136   // qkv W fp32 pitch (words)
#define WTP 68    // qkv Wt fp16 pitch (words = 136 halves)
#define QKP 68    // attn Q/K fp16 pitch (words = 136 halves)
#define VTP 100   // attn Vt/P fp16 pitch (words = 200 halves)

// ---------------------------------------------------------------------------
// Kernel 1: QKV projection (fp16 HMMA). grid=128, 256 threads, m16xn64/warp.
// smem words: Xs[0,8448) WsA[8448,25856) WsB[25856,43264) Wt[43264,51968)
// ---------------------------------------------------------------------------
#define QXS_W (TM * XPF)
#define QWS_W (DD * WPF)
#define QWT_OFF (QXS_W + 2 * QWS_W)
#define QKV_SMEM ((QWT_OFF + DD * WTP) * 4)   // 207872

__global__ __launch_bounds__(NT, 1) void qkv_kernel(
    const float* __restrict__ x,
    const float* __restrict__ Wq, const float* __restrict__ bq,
    const float* __restrict__ Wk, const float* __restrict__ bk,
    const float* __restrict__ Wv, const float* __restrict__ bv)
{
    extern __shared__ uint32_t smem[];
    const float* Xs  = (const float*)smem;
    const float* WsA = (const float*)(smem + QXS_W);
    const float* WsB = WsA + QWS_W;
    uint32_t*    Wt  = smem + QWT_OFF;          // fp16 [n][d], half2 words

    const uint32_t sb   = smem_u32(smem);
    const uint32_t xs_b = sb;
    const uint32_t wsA  = sb + QXS_W * 4;
    const uint32_t wsB  = wsA + QWS_W * 4;

    const int tid = threadIdx.x, w = tid >> 5, lane = tid & 31;
    const int gy = lane >> 2, gx = lane & 3;
    const int m0 = blockIdx.x * TM;
    const int r0 = 16 * (w & 3);
    const int c0 = 64 * (w >> 2);

    for (int i = tid; i < TM * 32; i += NT) {
        int m = i >> 5, c = (i & 31) << 2;
        cpa(xs_b + (uint32_t)(m * XPF + c) * 4, &x[(m0 + m) * DD + c], 16);
    }
    for (int i = tid; i < DD * 32; i += NT) {
        int d = i >> 5, c = (i & 31) << 2;
        cpa(wsA + (uint32_t)(d * WPF + c) * 4, &Wq[d * DD + c], 16);
    }
    CP_COMMIT();
    for (int i = tid; i < DD * 32; i += NT) {
        int d = i >> 5, c = (i & 31) << 2;
        cpa(wsB + (uint32_t)(d * WPF + c) * 4, &Wk[d * DD + c], 16);
    }
    CP_COMMIT();
    CP_WAIT(1);                     // X + Wq landed
    __syncthreads();

    // A fragments (fp16-packed) in registers, reused for Q/K/V. k0 = 16*ks.
    uint32_t a_all[8][4];
    #pragma unroll
    for (int ks = 0; ks < 8; ks++) {
        const int k0 = 16 * ks;
        float2 v0 = *(const float2*)&Xs[(r0 + gy) * XPF + k0 + 2 * gx];
        float2 v1 = *(const float2*)&Xs[(r0 + gy + 8) * XPF + k0 + 2 * gx];
        float2 v2 = *(const float2*)&Xs[(r0 + gy) * XPF + k0 + 8 + 2 * gx];
        float2 v3 = *(const float2*)&Xs[(r0 + gy + 8) * XPF + k0 + 8 + 2 * gx];
        a_all[ks][0] = pkh(v0.x, v0.y);
        a_all[ks][1] = pkh(v1.x, v1.y);
        a_all[ks][2] = pkh(v2.x, v2.y);
        a_all[ks][3] = pkh(v3.x, v3.y);
    }

    // W fp32 [d][n] -> Wt fp16 [n][d]
    auto cvtW = [&](const float* Wf) {
        for (int i = tid; i < DD * 32; i += NT) {
            int n = i & 127, d4 = (i >> 7) << 2;
            float w0 = Wf[(d4 + 0) * WPF + n];
            float w1 = Wf[(d4 + 1) * WPF + n];
            float w2 = Wf[(d4 + 2) * WPF + n];
            float w3 = Wf[(d4 + 3) * WPF + n];
            Wt[n * WTP + (d4 >> 1)]     = pkh(w0, w1);
            Wt[n * WTP + (d4 >> 1) + 1] = pkh(w2, w3);
        }
    };
    auto run_mma = [&](float acc[8][4]) {
        #pragma unroll
        for (int t = 0; t < 8; t++)
            #pragma unroll
            for (int c = 0; c < 4; c++) acc[t][c] = 0.f;
        #pragma unroll
        for (int ks = 0; ks < 8; ks++) {
            const int k0w = 8 * ks;
            #pragma unroll
            for (int t = 0; t < 8; t++) {
                int n0 = c0 + 8 * t;
                uint32_t b0 = Wt[(n0 + gy) * WTP + k0w + gx];
                uint32_t b1 = Wt[(n0 + gy) * WTP + k0w + 4 + gx];
                mma16(acc[t], a_all[ks], b0, b1);
            }
        }
    };

    cvtW(WsA);                       // Wq -> Wt
    __syncthreads();
    // WsA free: stream Wv in behind the Q MMA
    for (int i = tid; i < DD * 32; i += NT) {
        int d = i >> 5, c = (i & 31) << 2;
        cpa(wsA + (uint32_t)(d * WPF + c) * 4, &Wv[d * DD + c], 16);
    }
    CP_COMMIT();

    const float scale = 0.088388347648318447f;  // 1/sqrt(128)
    float acc[8][4];

    run_mma(acc);                    // Q
    #pragma unroll
    for (int t = 0; t < 8; t++) {
        int col = c0 + 8 * t + 2 * gx;
        float bx = bq[col], by = bq[col + 1];
        *(uint32_t*)&g_q[(size_t)(m0 + r0 + gy) * DD + col]     = pkh((acc[t][0] + bx) * scale, (acc[t][1] + by) * scale);
        *(uint32_t*)&g_q[(size_t)(m0 + r0 + gy + 8) * DD + col] = pkh((acc[t][2] + bx) * scale, (acc[t][3] + by) * scale);
    }

    CP_WAIT(1);                      // Wk landed (Wv may still be in flight)
    __syncthreads();                 // everyone done with Wt(Wq)
    cvtW(WsB);                       // Wk -> Wt
    __syncthreads();

    run_mma(acc);                    // K
    #pragma unroll
    for (int t = 0; t < 8; t++) {
        int col = c0 + 8 * t + 2 * gx;
        float bx = bk[col], by = bk[col + 1];
        *(uint32_t*)&g_k[(size_t)(m0 + r0 + gy) * DD + col]     = pkh(acc[t][0] + bx, acc[t][1] + by);
        *(uint32_t*)&g_k[(size_t)(m0 + r0 + gy + 8) * DD + col] = pkh(acc[t][2] + bx, acc[t][3] + by);
    }

    CP_WAIT(0);                      // Wv landed
    __syncthreads();
    cvtW(WsA);                       // Wv -> Wt
    __syncthreads();

    run_mma(acc);                    // V -> transposed global store
    {
        const int bb = m0 >> 12;                 // batch (tile never crosses)
        const int sbase = (m0 & (SS - 1)) + r0 + gy;
        __half* vt = g_vt + (size_t)bb * DD * SS;
        #pragma unroll
        for (int t = 0; t < 8; t++) {
            int col = c0 + 8 * t + 2 * gx;
            float bx = bv[col], by = bv[col + 1];
            vt[(size_t)(col)     * SS + sbase]     = __float2half_rn(acc[t][0] + bx);
            vt[(size_t)(col + 1) * SS + sbase]     = __float2half_rn(acc[t][1] + by);
            vt[(size_t)(col)     * SS + sbase + 8] = __float2half_rn(acc[t][2] + bx);
            vt[(size_t)(col + 1) * SS + sbase + 8] = __float2half_rn(acc[t][3] + by);
        }
    }
}

// ---------------------------------------------------------------------------
// Kernel 2: sliding-window attention (fp16 HMMA), band-aware warps,
// V^T copy overlapped with MMA1+softmax. grid=128, 256 threads.
// smem words: Qh[0,4352) Kh[4352,17408) Vt[17408,30208) Pu[30208,36608) rs
// ---------------------------------------------------------------------------
#define AQ_W (TM * QKP)              // 4352
#define AK_OFF AQ_W
#define AK_W (KU * QKP)              // 13056
#define AV_OFF (AK_OFF + AK_W)
#define AV_W (DD * VTP)              // 12800
#define AP_OFF (AV_OFF + AV_W)
#define AP_W (TM * VTP)              // 6400
#define ARS_OFF (AP_OFF + AP_W)
#define ATTN_SMEM ((ARS_OFF + 128) * 4)   // 146944

__global__ __launch_bounds__(NT, 1) void attn_kernel(float* __restrict__ out)
{
    extern __shared__ uint32_t smem[];
    const uint32_t* Qu = smem;                 // [64][68w]
    const uint32_t* Ku = smem + AK_OFF;        // [192][68w]
    const uint32_t* Vu = smem + AV_OFF;        // [128][100w]  (V^T: row=d, col=j)
    uint32_t*       Pu = smem + AP_OFF;        // [64][100w]   exp(s) fp16
    float*          rs = (float*)(smem + ARS_OFF);  // [2][64]

    const uint32_t sb  = smem_u32(smem);
    const uint32_t qb  = sb;
    const uint32_t kbuf = sb + AK_OFF * 4;
    const uint32_t vbuf = sb + AV_OFF * 4;

    const int tid = threadIdx.x, w = tid >> 5, lane = tid & 31;
    const int gy = lane >> 2, gx = lane & 3;
    const int b  = blockIdx.x >> 6;
    const int q0 = (blockIdx.x & 63) * TM;
    const int kb = q0 - HALF;

    const __half* qg  = g_q  + (size_t)b * SS * DD;
    const __half* kg  = g_k  + (size_t)b * SS * DD;
    const __half* vtg = g_vt + (size_t)b * DD * SS;

    // stage Q + K (group A), then V^T (group B)
    for (int i = tid; i < TM * 16; i += NT) {
        int m = i >> 4, ci = i & 15;
        cpa(qb + (uint32_t)(m * QKP + 4 * ci) * 4, qg + (size_t)(q0 + m) * DD + 8 * ci, 16);
    }
    for (int i = tid; i < KU * 16; i += NT) {
        int j = i >> 4, ci = i & 15;
        int key = kb + j;
        int ok = (key >= 0 && key < SS);
        cpa(kbuf + (uint32_t)(j * QKP + 4 * ci) * 4, kg + (size_t)(ok ? key : 0) * DD + 8 * ci, ok ? 16 : 0);
    }
    CP_COMMIT();
    for (int i = tid; i < DD * 24; i += NT) {
        int d = i / 24, ci = i % 24;
        int key0 = kb + 8 * ci;
        int ok = (key0 >= 0 && key0 + 8 <= SS);
        cpa(vbuf + (uint32_t)(d * VTP + 4 * ci) * 4, vtg + (size_t)d * SS + (ok ? key0 : 0), ok ? 16 : 0);
    }
    CP_COMMIT();
    CP_WAIT(1);                     // Q + K ready; V still streaming
    __syncthreads();

    const int r0   = 16 * (w & 3);          // row-group base
    const int half = w >> 2;                // band half (0/1)
    const int nb   = r0 + 72 * half;        // column base (9 tiles of 8)

    // ---- S = Q @ K^T : warp = m16 x n72, 8 k16-steps, 1-step prefetch ----
    {
        float sacc[9][4];
        #pragma unroll
        for (int t = 0; t < 9; t++)
            #pragma unroll
            for (int c = 0; c < 4; c++) sacc[t][c] = 0.f;

        uint32_t ap[4], bp[9][2];
        ap[0] = Qu[(r0 + gy) * QKP + gx];
        ap[1] = Qu[(r0 + gy + 8) * QKP + gx];
        ap[2] = Qu[(r0 + gy) * QKP + 4 + gx];
        ap[3] = Qu[(r0 + gy + 8) * QKP + 4 + gx];
        #pragma unroll
        for (int t = 0; t < 9; t++) {
            int n0 = nb + 8 * t;
            bp[t][0] = Ku[(n0 + gy) * QKP + gx];
            bp[t][1] = Ku[(n0 + gy) * QKP + 4 + gx];
        }
        #pragma unroll
        for (int ks = 0; ks < 8; ks++) {
            uint32_t an[4], bn[9][2];
            if (ks < 7) {
                const int k1w = 8 * (ks + 1);
                an[0] = Qu[(r0 + gy) * QKP + k1w + gx];
                an[1] = Qu[(r0 + gy + 8) * QKP + k1w + gx];
                an[2] = Qu[(r0 + gy) * QKP + k1w + 4 + gx];
                an[3] = Qu[(r0 + gy + 8) * QKP + k1w + 4 + gx];
                #pragma unroll
                for (int t = 0; t < 9; t++) {
                    int n0 = nb + 8 * t;
                    bn[t][0] = Ku[(n0 + gy) * QKP + k1w + gx];
                    bn[t][1] = Ku[(n0 + gy) * QKP + k1w + 4 + gx];
                }
            }
            #pragma unroll
            for (int t = 0; t < 9; t++) mma16(sacc[t], ap, bp[t][0], bp[t][1]);
            if (ks < 7) {
                #pragma unroll
                for (int q = 0; q < 4; q++) ap[q] = an[q];
                #pragma unroll
                for (int t = 0; t < 9; t++) { bp[t][0] = bn[t][0]; bp[t][1] = bn[t][1]; }
            }
        }

        // mask + exp in registers; write fp16 P; per-(half,row) sums
        float part[2] = {0.f, 0.f};
        #pragma unroll
        for (int t = 0; t < 9; t++) {
            #pragma unroll
            for (int h = 0; h < 2; h++) {
                int q  = r0 + gy + 8 * h;
                int j0 = nb + 8 * t + 2 * gx;
                float p0 = 0.f, p1 = 0.f;
                {
                    int j = j0, key = kb + j, dj = j - q;
                    if (dj >= 0 && dj <= 2 * HALF && key >= 0 && key < SS)
                        p0 = __expf(sacc[t][2 * h]);
                }
                {
                    int j = j0 + 1, key = kb + j, dj = j - q;
                    if (dj >= 0 && dj <= 2 * HALF && key >= 0 && key < SS)
                        p1 = __expf(sacc[t][2 * h + 1]);
                }
                part[h] += p0 + p1;
                Pu[q * VTP + (j0 >> 1)] = pkh(p0, p1);
            }
        }
        #pragma unroll
        for (int h = 0; h < 2; h++) {
            part[h] += __shfl_xor_sync(0xffffffffu, part[h], 1);
            part[h] += __shfl_xor_sync(0xffffffffu, part[h], 2);
        }
        if (gx == 0) {
            rs[64 * half + r0 + gy]     = part[0];
            rs[64 * half + r0 + gy + 8] = part[1];
        }
    }
    __syncthreads();                 // P + row sums visible
    CP_WAIT(0);                      // V^T landed
    __syncthreads();

    // ---- O = (P @ V) * inv[row] : warp = m16 x n64, 9 band k16-steps ----
    {
        const int d0 = 64 * half;
        float oacc[8][4];
        #pragma unroll
        for (int t = 0; t < 8; t++)
            #pragma unroll
            for (int c = 0; c < 4; c++) oacc[t][c] = 0.f;

        const int kw0 = r0 >> 1;     // word offset of band start (k = r0)
        uint32_t ap[4], bp[8][2];
        ap[0] = Pu[(r0 + gy) * VTP + kw0 + gx];
        ap[1] = Pu[(r0 + gy + 8) * VTP + kw0 + gx];
        ap[2] = Pu[(r0 + gy) * VTP + kw0 + 4 + gx];
        ap[3] = Pu[(r0 + gy + 8) * VTP + kw0 + 4 + gx];
        #pragma unroll
        for (int t = 0; t < 8; t++) {
            int n0 = d0 + 8 * t;
            bp[t][0] = Vu[(n0 + gy) * VTP + kw0 + gx];
            bp[t][1] = Vu[(n0 + gy) * VTP + kw0 + 4 + gx];
        }
        #pragma unroll
        for (int ks = 0; ks < 9; ks++) {
            uint32_t an[4], bn[8][2];
            if (ks < 8) {
                const int k1w = kw0 + 8 * (ks + 1);
                an[0] = Pu[(r0 + gy) * VTP + k1w + gx];
                an[1] = Pu[(r0 + gy + 8) * VTP + k1w + gx];
                an[2] = Pu[(r0 + gy) * VTP + k1w + 4 + gx];
                an[3] = Pu[(r0 + gy + 8) * VTP + k1w + 4 + gx];
                #pragma unroll
                for (int t = 0; t < 8; t++) {
                    int n0 = d0 + 8 * t;
                    bn[t][0] = Vu[(n0 + gy) * VTP + k1w + gx];
                    bn[t][1] = Vu[(n0 + gy) * VTP + k1w + 4 + gx];
                }
            }
            #pragma unroll
            for (int t = 0; t < 8; t++) mma16(oacc[t], ap, bp[t][0], bp[t][1]);
            if (ks < 8) {
                #pragma unroll
                for (int q = 0; q < 4; q++) ap[q] = an[q];
                #pragma unroll
                for (int t = 0; t < 8; t++) { bp[t][0] = bn[t][0]; bp[t][1] = bn[t][1]; }
            }
        }

        const float inv0 = 1.f / (rs[r0 + gy] + rs[64 + r0 + gy]);
        const float inv1 = 1.f / (rs[r0 + gy + 8] + rs[64 + r0 + gy + 8]);
        float* ob = out + (size_t)(b * SS + q0) * DD;
        #pragma unroll
        for (int t = 0; t < 8; t++) {
            int col = d0 + 8 * t + 2 * gx;
            *(float2*)&ob[(r0 + gy) * DD + col]     = make_float2(oacc[t][0] * inv0, oacc[t][1] * inv0);
            *(float2*)&ob[(r0 + gy + 8) * DD + col] = make_float2(oacc[t][2] * inv1, oacc[t][3] * inv1);
        }
    }
}

// ---------------------------------------------------------------------------
extern "C" void kernel_launch(void* const* d_in, const int* in_sizes, int n_in,
                              void* d_out, int out_size)
{
    const float* x  = (const float*)d_in[0];
    const float* Wq = (const float*)d_in[1];
    const float* bq = (const float*)d_in[2];
    const float* Wk = (const float*)d_in[3];
    const float* bk = (const float*)d_in[4];
    const float* Wv = (const float*)d_in[5];
    const float* bv = (const float*)d_in[6];
    float* out = (float*)d_out;

    cudaFuncSetAttribute(qkv_kernel,  cudaFuncAttributeMaxDynamicSharedMemorySize, QKV_SMEM);
    cudaFuncSetAttribute(attn_kernel, cudaFuncAttributeMaxDynamicSharedMemorySize, ATTN_SMEM);

    qkv_kernel<<<(BB * SS) / TM, NT, QKV_SMEM>>>(x, Wq, bq, Wk, bk, Wv, bv);
    attn_kernel<<<BB * (SS / TM), NT, ATTN_SMEM>>>(out);
}